// round 13
// baseline (speedup 1.0000x reference)
#include <cuda_runtime.h>
#include <cuda_bf16.h>
#include <cstdint>

// Problem constants (fixed by the reference)
#define B_      4
#define NQ_     1024
#define NC_     16384
#define D_      1024
#define TOPN    5
#define NCHUNK  8
#define CHUNK   (NC_ / NCHUNK)   // 2048
#define NROWS   (B_ * NQ_)       // 4096
#define NRESC   16               // candidates rescored per row
#define NCAND   (NCHUNK * TOPN)  // 40 screened keys per row

// Screen tiling (mma.sync path — tcgen05 PTX rejected: harness emits compute_103,
// arch-specific tcgen05 needs compute_103a)
#define KT      64                        // k-tile (bf16 elems)
#define NKT     (D_ / KT)                 // 16
#define ROWB    144                       // bytes/row in smem tile (8 chunks + pad)
#define STG_A   (128 * ROWB)              // 18432 B per A tile
#define STG     (2 * STG_A)               // 36864 B per stage (A+B)
#define SM_DT   (2 * STG)                 // 73728: dt offset
#define SM_CSQ  (SM_DT + 128 * 33 * 4)    // 90624: csq offset
#define SM_SCRN (SM_CSQ + CHUNK * 4)      // 98816 total dynamic smem

// Rescore smem layout (dynamic): q row + 16 candidate rows
#define RS_Q     0                        // 4096 B
#define RS_CAND  4096                     // 16 x 4096 B = 65536 B
#define RS_TOTAL (RS_CAND + NRESC * D_ * 4)   // 69632 B

// ---------------------------------------------------------------------------
// Scratch (no allocations allowed -> __device__ globals, device-code refs only)
// ---------------------------------------------------------------------------
__device__ float          g_qproj[NROWS * D_];            // fp32 q_proj
__device__ __nv_bfloat16  g_qp_bf[NROWS * D_];            // bf16 q_proj
__device__ __nv_bfloat16  g_ctx_bf[(size_t)B_ * NC_ * D_];// bf16 ctx
__device__ float          g_csq[B_ * NC_];
__device__ unsigned long long g_cand[NROWS * NCAND];

// ---------------------------------------------------------------------------
__device__ __forceinline__ void insert5(unsigned long long* run, unsigned long long key) {
    if (key < run[4]) {
        run[4] = key;
        if (run[4] < run[3]) { unsigned long long t = run[3]; run[3] = run[4]; run[4] = t; }
        if (run[3] < run[2]) { unsigned long long t = run[2]; run[2] = run[3]; run[3] = t; }
        if (run[2] < run[1]) { unsigned long long t = run[1]; run[1] = run[2]; run[2] = t; }
        if (run[1] < run[0]) { unsigned long long t = run[0]; run[0] = run[1]; run[1] = t; }
    }
}

__device__ __forceinline__ uint32_t smem_u32(const void* p) {
    uint32_t r;
    asm("{ .reg .u64 t; cvta.to.shared.u64 t, %1; cvt.u32.u64 %0, t; }" : "=r"(r) : "l"(p));
    return r;
}

__device__ __forceinline__ void cpa16(uint32_t dst, const void* src) {
    asm volatile("cp.async.cg.shared.global [%0], [%1], 16;" :: "r"(dst), "l"(src));
}

// Error-free-transformation helpers (valid under round-to-nearest):
__device__ __forceinline__ void two_sum(float a, float b, float& s, float& e) {
    s = __fadd_rn(a, b);
    float bb = __fsub_rn(s, a);
    float t1 = __fsub_rn(s, bb);
    float t2 = __fsub_rn(a, t1);
    float t3 = __fsub_rn(b, bb);
    e = __fadd_rn(t2, t3);
}

// EFT accumulation of one squared difference (q - c)^2 into (hi, lo):
// exact except e*e (<= 2^-48 relative) and lo's own fp32 rounding (~1e-9 abs).
__device__ __forceinline__ void acc_sqdiff(float q, float c, float& hi, float& lo) {
    float s, e;
    two_sum(q, __fmul_rn(-1.0f, c), s, e);
    float p  = __fmul_rn(s, s);
    float pe = __fmaf_rn(s, s, -p);
    float small = __fmaf_rn(__fmul_rn(2.0f, s), e, pe);
    float s1, e1;
    two_sum(hi, p, s1, e1);
    hi = s1;
    lo = __fadd_rn(lo, __fadd_rn(e1, small));
}

// ---------------------------------------------------------------------------
// Kernel 1: q_proj = Q @ W^T + b (fp32 SIMT SGEMM) + bf16 copy for the screen.
// Correctness-load-bearing rounding realization; do not change.
// ---------------------------------------------------------------------------
__global__ __launch_bounds__(256, 2) void qproj_kernel(
    const float* __restrict__ Q, const float* __restrict__ W,
    const float* __restrict__ bias)
{
    __shared__ __align__(16) float As[8][132];
    __shared__ __align__(16) float Bs[8][132];

    const int t  = threadIdx.x;
    const int tx = t & 15, ty = t >> 4;
    const int m0 = blockIdx.y * 128, n0 = blockIdx.x * 128;
    const int lr = t >> 1;
    const int lk = (t & 1) * 4;

    const float* Ap = Q + (size_t)(m0 + lr) * D_ + lk;
    const float* Bp = W + (size_t)(n0 + lr) * D_ + lk;

    float acc[8][8];
    #pragma unroll
    for (int i = 0; i < 8; i++)
        #pragma unroll
        for (int j = 0; j < 8; j++) acc[i][j] = 0.0f;

    for (int k0 = 0; k0 < D_; k0 += 8) {
        float4 av = *(const float4*)(Ap + k0);
        float4 bv = *(const float4*)(Bp + k0);
        __syncthreads();
        As[lk + 0][lr] = av.x; As[lk + 1][lr] = av.y;
        As[lk + 2][lr] = av.z; As[lk + 3][lr] = av.w;
        Bs[lk + 0][lr] = bv.x; Bs[lk + 1][lr] = bv.y;
        Bs[lk + 2][lr] = bv.z; Bs[lk + 3][lr] = bv.w;
        __syncthreads();
        #pragma unroll
        for (int kk = 0; kk < 8; kk++) {
            float a[8], b[8];
            *(float4*)(a)     = *(const float4*)(&As[kk][ty * 8]);
            *(float4*)(a + 4) = *(const float4*)(&As[kk][ty * 8 + 4]);
            *(float4*)(b)     = *(const float4*)(&Bs[kk][tx * 8]);
            *(float4*)(b + 4) = *(const float4*)(&Bs[kk][tx * 8 + 4]);
            #pragma unroll
            for (int i = 0; i < 8; i++)
                #pragma unroll
                for (int j = 0; j < 8; j++)
                    acc[i][j] = fmaf(a[i], b[j], acc[i][j]);
        }
    }

    float bj[8];
    #pragma unroll
    for (int j = 0; j < 8; j++) bj[j] = bias[n0 + tx * 8 + j];
    #pragma unroll
    for (int i = 0; i < 8; i++) {
        int row = m0 + ty * 8 + i;
        float o[8];
        #pragma unroll
        for (int j = 0; j < 8; j++) o[j] = __fadd_rn(acc[i][j], bj[j]);
        *(float4*)(g_qproj + (size_t)row * D_ + n0 + tx * 8)     = make_float4(o[0], o[1], o[2], o[3]);
        *(float4*)(g_qproj + (size_t)row * D_ + n0 + tx * 8 + 4) = make_float4(o[4], o[5], o[6], o[7]);
        __nv_bfloat162* dstb = (__nv_bfloat162*)(g_qp_bf + (size_t)row * D_ + n0 + tx * 8);
        dstb[0] = __floats2bfloat162_rn(o[0], o[1]);
        dstb[1] = __floats2bfloat162_rn(o[2], o[3]);
        dstb[2] = __floats2bfloat162_rn(o[4], o[5]);
        dstb[3] = __floats2bfloat162_rn(o[6], o[7]);
    }
}

// ---------------------------------------------------------------------------
// Kernel 2 (fused): one pass over ctx -> bf16 copy + squared row norms.
// ---------------------------------------------------------------------------
__global__ __launch_bounds__(256) void ctxprep_kernel(const float* __restrict__ ctx)
{
    int row  = (blockIdx.x * blockDim.x + threadIdx.x) >> 5;
    int lane = threadIdx.x & 31;
    if (row >= B_ * NC_) return;
    const float4* p = (const float4*)(ctx + (size_t)row * D_);
    uint2* ob = (uint2*)(g_ctx_bf + (size_t)row * D_);
    float s = 0.0f;
    #pragma unroll
    for (int it = 0; it < D_ / 4 / 32; it++) {
        float4 v = p[lane + it * 32];
        s += v.x * v.x + v.y * v.y + v.z * v.z + v.w * v.w;
        union { __nv_bfloat162 h[2]; uint2 u; } pk;
        pk.h[0] = __floats2bfloat162_rn(v.x, v.y);
        pk.h[1] = __floats2bfloat162_rn(v.z, v.w);
        ob[lane + it * 32] = pk.u;
    }
    #pragma unroll
    for (int off = 16; off; off >>= 1) s += __shfl_xor_sync(0xffffffffu, s, off);
    if (lane == 0) g_csq[row] = s;
}

// ---------------------------------------------------------------------------
// Kernel 3: bf16 mma.sync tensor-core screen, 2-stage cp.async pipeline.
// (round-11 version — passing; crossbar-bound, tcgen05 unavailable in build)
// ---------------------------------------------------------------------------
__global__ __launch_bounds__(256) void screen_kernel()
{
    extern __shared__ __align__(16) char dsm[];
    float (*dt)[33] = (float(*)[33])(dsm + SM_DT);
    float* s_csq    = (float*)(dsm + SM_CSQ);
    const uint32_t smb = smem_u32(dsm);

    const int t    = threadIdx.x;
    const int lane = t & 31;
    const int w    = t >> 5;
    const int wm   = w >> 2;
    const int wn   = w & 3;
    const int ch   = blockIdx.x;
    const int qb   = blockIdx.y;
    const int b    = blockIdx.z;
    const int m0   = b * NQ_ + qb * 128;
    const int c0   = ch * CHUNK;

    for (int i = t; i < CHUNK; i += 256) s_csq[i] = g_csq[b * NC_ + c0 + i];

    int ldr[4], ldc[4];
    #pragma unroll
    for (int i = 0; i < 4; i++) {
        int c = t + i * 256;
        ldr[i] = c >> 3;
        ldc[i] = c & 7;
    }

    const int lm_row  = lane & 15;
    const int lm_half = lane >> 4;

    unsigned long long run[5] = { ~0ull, ~0ull, ~0ull, ~0ull, ~0ull };

    const __nv_bfloat16* gA = g_qp_bf + (size_t)m0 * D_;

    for (int nt = 0; nt < CHUNK / 128; nt++) {
        const __nv_bfloat16* gB = g_ctx_bf + ((size_t)b * NC_ + c0 + nt * 128) * D_;

        float acc[4][4][4];
        #pragma unroll
        for (int fm = 0; fm < 4; fm++)
            #pragma unroll
            for (int fn = 0; fn < 4; fn++)
                #pragma unroll
                for (int v = 0; v < 4; v++) acc[fm][fn][v] = 0.0f;

        #pragma unroll
        for (int i = 0; i < 4; i++) {
            cpa16(smb + ldr[i] * ROWB + ldc[i] * 16,
                  gA + (size_t)ldr[i] * D_ + ldc[i] * 8);
            cpa16(smb + STG_A + ldr[i] * ROWB + ldc[i] * 16,
                  gB + (size_t)ldr[i] * D_ + ldc[i] * 8);
        }
        asm volatile("cp.async.commit_group;");

        for (int kt = 0; kt < NKT; kt++) {
            asm volatile("cp.async.wait_group 0;");
            __syncthreads();
            if (kt + 1 < NKT) {
                uint32_t sb = smb + ((kt + 1) & 1) * STG;
                int koff = (kt + 1) * KT;
                #pragma unroll
                for (int i = 0; i < 4; i++) {
                    cpa16(sb + ldr[i] * ROWB + ldc[i] * 16,
                          gA + (size_t)ldr[i] * D_ + koff + ldc[i] * 8);
                    cpa16(sb + STG_A + ldr[i] * ROWB + ldc[i] * 16,
                          gB + (size_t)ldr[i] * D_ + koff + ldc[i] * 8);
                }
                asm volatile("cp.async.commit_group;");
            }
            const uint32_t bufA = smb + (kt & 1) * STG;
            const uint32_t bufB = bufA + STG_A;

            #pragma unroll
            for (int kh = 0; kh < 4; kh++) {
                uint32_t a[4][4];
                #pragma unroll
                for (int fm = 0; fm < 4; fm++) {
                    int row = wm * 64 + fm * 16 + lm_row;
                    uint32_t addr = bufA + (uint32_t)(row * ROWB + (kh * 2 + lm_half) * 16);
                    asm volatile(
                        "ldmatrix.sync.aligned.m8n8.x4.shared.b16 {%0,%1,%2,%3}, [%4];"
                        : "=r"(a[fm][0]), "=r"(a[fm][1]), "=r"(a[fm][2]), "=r"(a[fm][3])
                        : "r"(addr));
                }
                #pragma unroll
                for (int fn = 0; fn < 4; fn++) {
                    int n = wn * 32 + fn * 8 + (lane >> 2);
                    uint32_t baddr = bufB + (uint32_t)(n * ROWB + kh * 32 + (lane & 3) * 4);
                    uint32_t b0, b1;
                    asm volatile("ld.shared.b32 %0, [%1];" : "=r"(b0) : "r"(baddr));
                    asm volatile("ld.shared.b32 %0, [%1];" : "=r"(b1) : "r"(baddr + 16));
                    #pragma unroll
                    for (int fm = 0; fm < 4; fm++) {
                        asm volatile(
                            "mma.sync.aligned.m16n8k16.row.col.f32.bf16.bf16.f32 "
                            "{%0,%1,%2,%3},{%4,%5,%6,%7},{%8,%9},{%0,%1,%2,%3};"
                            : "+f"(acc[fm][fn][0]), "+f"(acc[fm][fn][1]),
                              "+f"(acc[fm][fn][2]), "+f"(acc[fm][fn][3])
                            : "r"(a[fm][0]), "r"(a[fm][1]), "r"(a[fm][2]), "r"(a[fm][3]),
                              "r"(b0), "r"(b1));
                    }
                }
            }
        }

        #pragma unroll
        for (int p = 0; p < 4; p++) {
            if (wn == p) {
                #pragma unroll
                for (int fm = 0; fm < 4; fm++) {
                    int r0 = wm * 64 + fm * 16 + (lane >> 2);
                    #pragma unroll
                    for (int ff = 0; ff < 4; ff++) {
                        int cl = ff * 8 + (lane & 3) * 2;
                        dt[r0][cl]         = acc[fm][ff][0];
                        dt[r0][cl + 1]     = acc[fm][ff][1];
                        dt[r0 + 8][cl]     = acc[fm][ff][2];
                        dt[r0 + 8][cl + 1] = acc[fm][ff][3];
                    }
                }
            }
            __syncthreads();
            if (t < 128) {
                int base = nt * 128 + p * 32;
                #pragma unroll 8
                for (int c = 0; c < 32; c++) {
                    float s = __fmaf_rn(-2.0f, dt[t][c], s_csq[base + c]);
                    unsigned u = __float_as_uint(s);
                    u ^= (unsigned)((int)u >> 31) | 0x80000000u;
                    unsigned long long key =
                        ((unsigned long long)u << 32) | (unsigned)(c0 + base + c);
                    insert5(run, key);
                }
            }
            __syncthreads();
        }
    }

    if (t < 128) {
        size_t base = ((size_t)(m0 + t) * NCHUNK + ch) * TOPN;
        #pragma unroll
        for (int i = 0; i < TOPN; i++) g_cand[base + i] = run[i];
    }
}

// ---------------------------------------------------------------------------
// Kernel 4: rescore. NEW: after the t==0 merge picks the top-16 indices, ALL
// 16 candidate rows (64 KB) are bulk-staged into dynamic smem via cp.async in
// one pipelined burst (previously each warp walked its row with 8 SERIAL
// scattered ~600-cycle global round trips — that was the 287us). EFT loop then
// runs entirely from smem. Arithmetic unchanged (fp64-grade ordering).
// Output: out[0..20479] = distances, out[20480..40959] = indices as float.
// ---------------------------------------------------------------------------
__global__ __launch_bounds__(512) void rescore_kernel(
    const float* __restrict__ ctx, float* __restrict__ out, int out_size)
{
    extern __shared__ __align__(16) char rsm[];
    float* s_q    = (float*)(rsm + RS_Q);
    float* s_cand = (float*)(rsm + RS_CAND);     // [NRESC][D_]
    __shared__ unsigned long long s_keys[NCAND];
    __shared__ int    s_idx[NRESC];
    __shared__ double s_d2[NRESC];

    const int row  = blockIdx.x;
    const int b    = row / NQ_;
    const int t    = threadIdx.x;
    const int warp = t >> 5;
    const int lane = t & 31;

    if (t < NCAND) s_keys[t] = g_cand[(size_t)row * NCAND + t];
    {
        const float4* src = (const float4*)(g_qproj + (size_t)row * D_);
        float4* dst = (float4*)s_q;
        for (int i = t; i < D_ / 4; i += 512) dst[i] = src[i];
    }
    __syncthreads();

    if (t == 0) {
        unsigned long long best[NRESC];
        #pragma unroll
        for (int i = 0; i < NRESC; i++) best[i] = ~0ull;
        #pragma unroll
        for (int i = 0; i < NCAND; i++) {
            unsigned long long key = s_keys[i];
            if (key < best[NRESC - 1]) {
                int j = NRESC - 1;
                while (j > 0 && best[j - 1] > key) { best[j] = best[j - 1]; j--; }
                best[j] = key;
            }
        }
        #pragma unroll
        for (int i = 0; i < NRESC; i++) s_idx[i] = (int)(best[i] & 0xffffffffu);
    }
    __syncthreads();

    // bulk cp.async stage of all 16 candidate rows: 4096 x 16B chunks,
    // 8 per thread, one commit/wait (full MLP, no serial round trips)
    {
        const uint32_t scb = smem_u32(s_cand);
        #pragma unroll
        for (int i = 0; i < 8; i++) {
            int cid = t + i * 512;           // 0..4095
            int s   = cid >> 8;              // candidate 0..15 (256 chunks each)
            int off = cid & 255;             // 16B chunk within row
            const float* src = ctx + ((size_t)b * NC_ + s_idx[s]) * D_ + off * 4;
            cpa16(scb + (uint32_t)(s * D_ * 4 + off * 16), src);
        }
        asm volatile("cp.async.commit_group;");
        asm volatile("cp.async.wait_group 0;");
    }
    __syncthreads();

    {
        const float4* c4 = (const float4*)(s_cand + (size_t)warp * D_);
        const float4* q4 = (const float4*)s_q;
        float hi = 0.0f, lo = 0.0f;
        #pragma unroll
        for (int it = 0; it < D_ / 128; it++) {
            float4 qv = q4[lane + it * 32];
            float4 cv = c4[lane + it * 32];
            acc_sqdiff(qv.x, cv.x, hi, lo);
            acc_sqdiff(qv.y, cv.y, hi, lo);
            acc_sqdiff(qv.z, cv.z, hi, lo);
            acc_sqdiff(qv.w, cv.w, hi, lo);
        }
        double acc = (double)hi + (double)lo;
        #pragma unroll
        for (int off = 16; off; off >>= 1)
            acc += __shfl_xor_sync(0xffffffffu, acc, off);
        if (lane == 0) s_d2[warp] = acc;
    }
    __syncthreads();

    if (t == 0) {
        double d2l[NRESC]; int idl[NRESC];
        #pragma unroll
        for (int i = 0; i < NRESC; i++) { d2l[i] = s_d2[i]; idl[i] = s_idx[i]; }
        const bool write_idx = (out_size >= 2 * NROWS * TOPN);
        #pragma unroll
        for (int k = 0; k < TOPN; k++) {
            int m = k;
            for (int j = k + 1; j < NRESC; j++)
                if (d2l[j] < d2l[m] || (d2l[j] == d2l[m] && idl[j] < idl[m])) m = j;
            double td = d2l[m]; int ti = idl[m];
            d2l[m] = d2l[k]; idl[m] = idl[k];
            d2l[k] = td; idl[k] = ti;
            out[row * TOPN + k] = (float)sqrt(td);
            if (write_idx)
                out[NROWS * TOPN + row * TOPN + k] = (float)ti;
        }
    }
}

// ---------------------------------------------------------------------------
// Launch
// ---------------------------------------------------------------------------
extern "C" void kernel_launch(void* const* d_in, const int* in_sizes, int n_in,
                              void* d_out, int out_size)
{
    const float* Q    = (const float*)d_in[0];   // [4,1024,1024]
    const float* C    = (const float*)d_in[1];   // [4,16384,1024]
    const float* W    = (const float*)d_in[2];   // [1024,1024]
    const float* bias = (const float*)d_in[3];   // [1024]
    float* out = (float*)d_out;

    cudaFuncSetAttribute(screen_kernel,
                         cudaFuncAttributeMaxDynamicSharedMemorySize, SM_SCRN);
    cudaFuncSetAttribute(rescore_kernel,
                         cudaFuncAttributeMaxDynamicSharedMemorySize, RS_TOTAL);

    qproj_kernel<<<dim3(D_ / 128, NROWS / 128), 256>>>(Q, W, bias);
    ctxprep_kernel<<<(B_ * NC_ * 32 + 255) / 256, 256>>>(C);
    screen_kernel<<<dim3(NCHUNK, NQ_ / 128, B_), 256, SM_SCRN>>>();
    rescore_kernel<<<NROWS, 512, RS_TOTAL>>>(C, out, out_size);
}

// round 14
// speedup vs baseline: 1.0189x; 1.0189x over previous
#include <cuda_runtime.h>
#include <cuda_bf16.h>
#include <cstdint>

// Problem constants (fixed by the reference)
#define B_      4
#define NQ_     1024
#define NC_     16384
#define D_      1024
#define TOPN    5
#define NCHUNK  8
#define CHUNK   (NC_ / NCHUNK)   // 2048
#define NROWS   (B_ * NQ_)       // 4096
#define NRESC   16               // candidates rescored per row
#define NCAND   (NCHUNK * TOPN)  // 40 screened keys per row

// Screen tiling (mma.sync path — tcgen05 PTX rejected: harness emits compute_103,
// arch-specific tcgen05 needs compute_103a)
#define KT      64                        // k-tile (bf16 elems)
#define NKT     (D_ / KT)                 // 16
#define ROWB    144                       // bytes/row in smem tile (8 chunks + pad)
#define STG_A   (128 * ROWB)              // 18432 B per A tile
#define STG     (2 * STG_A)               // 36864 B per stage (A+B)
#define SM_DT   (2 * STG)                 // 73728: dt offset
#define SM_CSQ  (SM_DT + 128 * 33 * 4)    // 90624: csq offset
#define SM_SCRN (SM_CSQ + CHUNK * 4)      // 98816 total dynamic smem

// ---------------------------------------------------------------------------
// Scratch (no allocations allowed -> __device__ globals, device-code refs only)
// ---------------------------------------------------------------------------
__device__ float          g_qproj[NROWS * D_];            // fp32 q_proj
__device__ __nv_bfloat16  g_qp_bf[NROWS * D_];            // bf16 q_proj
__device__ __nv_bfloat16  g_ctx_bf[(size_t)B_ * NC_ * D_];// bf16 ctx
__device__ float          g_csq[B_ * NC_];
__device__ unsigned long long g_cand[NROWS * NCAND];

// ---------------------------------------------------------------------------
__device__ __forceinline__ void insert5(unsigned long long* run, unsigned long long key) {
    if (key < run[4]) {
        run[4] = key;
        if (run[4] < run[3]) { unsigned long long t = run[3]; run[3] = run[4]; run[4] = t; }
        if (run[3] < run[2]) { unsigned long long t = run[2]; run[2] = run[3]; run[3] = t; }
        if (run[2] < run[1]) { unsigned long long t = run[1]; run[1] = run[2]; run[2] = t; }
        if (run[1] < run[0]) { unsigned long long t = run[0]; run[0] = run[1]; run[1] = t; }
    }
}

__device__ __forceinline__ uint32_t smem_u32(const void* p) {
    uint32_t r;
    asm("{ .reg .u64 t; cvta.to.shared.u64 t, %1; cvt.u32.u64 %0, t; }" : "=r"(r) : "l"(p));
    return r;
}

__device__ __forceinline__ void cpa16(uint32_t dst, const void* src) {
    asm volatile("cp.async.cg.shared.global [%0], [%1], 16;" :: "r"(dst), "l"(src));
}

// Error-free-transformation helpers (valid under round-to-nearest):
__device__ __forceinline__ void two_sum(float a, float b, float& s, float& e) {
    s = __fadd_rn(a, b);
    float bb = __fsub_rn(s, a);
    float t1 = __fsub_rn(s, bb);
    float t2 = __fsub_rn(a, t1);
    float t3 = __fsub_rn(b, bb);
    e = __fadd_rn(t2, t3);
}

// EFT accumulation of one squared difference (q - c)^2 into (hi, lo):
// exact except e*e (<= 2^-48 relative) and lo's own fp32 rounding (~1e-9 abs).
__device__ __forceinline__ void acc_sqdiff(float q, float c, float& hi, float& lo) {
    float s, e;
    two_sum(q, __fmul_rn(-1.0f, c), s, e);
    float p  = __fmul_rn(s, s);
    float pe = __fmaf_rn(s, s, -p);
    float small = __fmaf_rn(__fmul_rn(2.0f, s), e, pe);
    float s1, e1;
    two_sum(hi, p, s1, e1);
    hi = s1;
    lo = __fadd_rn(lo, __fadd_rn(e1, small));
}

// ---------------------------------------------------------------------------
// Kernel 1: q_proj = Q @ W^T + b (fp32 SIMT SGEMM) + bf16 copy for the screen.
// Correctness-load-bearing rounding realization; do not change.
// ---------------------------------------------------------------------------
__global__ __launch_bounds__(256, 2) void qproj_kernel(
    const float* __restrict__ Q, const float* __restrict__ W,
    const float* __restrict__ bias)
{
    __shared__ __align__(16) float As[8][132];
    __shared__ __align__(16) float Bs[8][132];

    const int t  = threadIdx.x;
    const int tx = t & 15, ty = t >> 4;
    const int m0 = blockIdx.y * 128, n0 = blockIdx.x * 128;
    const int lr = t >> 1;
    const int lk = (t & 1) * 4;

    const float* Ap = Q + (size_t)(m0 + lr) * D_ + lk;
    const float* Bp = W + (size_t)(n0 + lr) * D_ + lk;

    float acc[8][8];
    #pragma unroll
    for (int i = 0; i < 8; i++)
        #pragma unroll
        for (int j = 0; j < 8; j++) acc[i][j] = 0.0f;

    for (int k0 = 0; k0 < D_; k0 += 8) {
        float4 av = *(const float4*)(Ap + k0);
        float4 bv = *(const float4*)(Bp + k0);
        __syncthreads();
        As[lk + 0][lr] = av.x; As[lk + 1][lr] = av.y;
        As[lk + 2][lr] = av.z; As[lk + 3][lr] = av.w;
        Bs[lk + 0][lr] = bv.x; Bs[lk + 1][lr] = bv.y;
        Bs[lk + 2][lr] = bv.z; Bs[lk + 3][lr] = bv.w;
        __syncthreads();
        #pragma unroll
        for (int kk = 0; kk < 8; kk++) {
            float a[8], b[8];
            *(float4*)(a)     = *(const float4*)(&As[kk][ty * 8]);
            *(float4*)(a + 4) = *(const float4*)(&As[kk][ty * 8 + 4]);
            *(float4*)(b)     = *(const float4*)(&Bs[kk][tx * 8]);
            *(float4*)(b + 4) = *(const float4*)(&Bs[kk][tx * 8 + 4]);
            #pragma unroll
            for (int i = 0; i < 8; i++)
                #pragma unroll
                for (int j = 0; j < 8; j++)
                    acc[i][j] = fmaf(a[i], b[j], acc[i][j]);
        }
    }

    float bj[8];
    #pragma unroll
    for (int j = 0; j < 8; j++) bj[j] = bias[n0 + tx * 8 + j];
    #pragma unroll
    for (int i = 0; i < 8; i++) {
        int row = m0 + ty * 8 + i;
        float o[8];
        #pragma unroll
        for (int j = 0; j < 8; j++) o[j] = __fadd_rn(acc[i][j], bj[j]);
        *(float4*)(g_qproj + (size_t)row * D_ + n0 + tx * 8)     = make_float4(o[0], o[1], o[2], o[3]);
        *(float4*)(g_qproj + (size_t)row * D_ + n0 + tx * 8 + 4) = make_float4(o[4], o[5], o[6], o[7]);
        __nv_bfloat162* dstb = (__nv_bfloat162*)(g_qp_bf + (size_t)row * D_ + n0 + tx * 8);
        dstb[0] = __floats2bfloat162_rn(o[0], o[1]);
        dstb[1] = __floats2bfloat162_rn(o[2], o[3]);
        dstb[2] = __floats2bfloat162_rn(o[4], o[5]);
        dstb[3] = __floats2bfloat162_rn(o[6], o[7]);
    }
}

// ---------------------------------------------------------------------------
// Kernel 2 (fused): one pass over ctx -> bf16 copy + squared row norms.
// Independent of qproj -> launched on a forked stream, overlaps with it.
// ---------------------------------------------------------------------------
__global__ __launch_bounds__(256) void ctxprep_kernel(const float* __restrict__ ctx)
{
    int row  = (blockIdx.x * blockDim.x + threadIdx.x) >> 5;
    int lane = threadIdx.x & 31;
    if (row >= B_ * NC_) return;
    const float4* p = (const float4*)(ctx + (size_t)row * D_);
    uint2* ob = (uint2*)(g_ctx_bf + (size_t)row * D_);
    float s = 0.0f;
    #pragma unroll
    for (int it = 0; it < D_ / 4 / 32; it++) {
        float4 v = p[lane + it * 32];
        s += v.x * v.x + v.y * v.y + v.z * v.z + v.w * v.w;
        union { __nv_bfloat162 h[2]; uint2 u; } pk;
        pk.h[0] = __floats2bfloat162_rn(v.x, v.y);
        pk.h[1] = __floats2bfloat162_rn(v.z, v.w);
        ob[lane + it * 32] = pk.u;
    }
    #pragma unroll
    for (int off = 16; off; off >>= 1) s += __shfl_xor_sync(0xffffffffu, s, off);
    if (lane == 0) g_csq[row] = s;
}

// ---------------------------------------------------------------------------
// Kernel 3: bf16 mma.sync tensor-core screen, 2-stage cp.async pipeline.
// (round-11 version — crossbar-bound; tcgen05 unavailable in this build)
// ---------------------------------------------------------------------------
__global__ __launch_bounds__(256) void screen_kernel()
{
    extern __shared__ __align__(16) char dsm[];
    float (*dt)[33] = (float(*)[33])(dsm + SM_DT);
    float* s_csq    = (float*)(dsm + SM_CSQ);
    const uint32_t smb = smem_u32(dsm);

    const int t    = threadIdx.x;
    const int lane = t & 31;
    const int w    = t >> 5;
    const int wm   = w >> 2;
    const int wn   = w & 3;
    const int ch   = blockIdx.x;
    const int qb   = blockIdx.y;
    const int b    = blockIdx.z;
    const int m0   = b * NQ_ + qb * 128;
    const int c0   = ch * CHUNK;

    for (int i = t; i < CHUNK; i += 256) s_csq[i] = g_csq[b * NC_ + c0 + i];

    int ldr[4], ldc[4];
    #pragma unroll
    for (int i = 0; i < 4; i++) {
        int c = t + i * 256;
        ldr[i] = c >> 3;
        ldc[i] = c & 7;
    }

    const int lm_row  = lane & 15;
    const int lm_half = lane >> 4;

    unsigned long long run[5] = { ~0ull, ~0ull, ~0ull, ~0ull, ~0ull };

    const __nv_bfloat16* gA = g_qp_bf + (size_t)m0 * D_;

    for (int nt = 0; nt < CHUNK / 128; nt++) {
        const __nv_bfloat16* gB = g_ctx_bf + ((size_t)b * NC_ + c0 + nt * 128) * D_;

        float acc[4][4][4];
        #pragma unroll
        for (int fm = 0; fm < 4; fm++)
            #pragma unroll
            for (int fn = 0; fn < 4; fn++)
                #pragma unroll
                for (int v = 0; v < 4; v++) acc[fm][fn][v] = 0.0f;

        #pragma unroll
        for (int i = 0; i < 4; i++) {
            cpa16(smb + ldr[i] * ROWB + ldc[i] * 16,
                  gA + (size_t)ldr[i] * D_ + ldc[i] * 8);
            cpa16(smb + STG_A + ldr[i] * ROWB + ldc[i] * 16,
                  gB + (size_t)ldr[i] * D_ + ldc[i] * 8);
        }
        asm volatile("cp.async.commit_group;");

        for (int kt = 0; kt < NKT; kt++) {
            asm volatile("cp.async.wait_group 0;");
            __syncthreads();
            if (kt + 1 < NKT) {
                uint32_t sb = smb + ((kt + 1) & 1) * STG;
                int koff = (kt + 1) * KT;
                #pragma unroll
                for (int i = 0; i < 4; i++) {
                    cpa16(sb + ldr[i] * ROWB + ldc[i] * 16,
                          gA + (size_t)ldr[i] * D_ + koff + ldc[i] * 8);
                    cpa16(sb + STG_A + ldr[i] * ROWB + ldc[i] * 16,
                          gB + (size_t)ldr[i] * D_ + koff + ldc[i] * 8);
                }
                asm volatile("cp.async.commit_group;");
            }
            const uint32_t bufA = smb + (kt & 1) * STG;
            const uint32_t bufB = bufA + STG_A;

            #pragma unroll
            for (int kh = 0; kh < 4; kh++) {
                uint32_t a[4][4];
                #pragma unroll
                for (int fm = 0; fm < 4; fm++) {
                    int row = wm * 64 + fm * 16 + lm_row;
                    uint32_t addr = bufA + (uint32_t)(row * ROWB + (kh * 2 + lm_half) * 16);
                    asm volatile(
                        "ldmatrix.sync.aligned.m8n8.x4.shared.b16 {%0,%1,%2,%3}, [%4];"
                        : "=r"(a[fm][0]), "=r"(a[fm][1]), "=r"(a[fm][2]), "=r"(a[fm][3])
                        : "r"(addr));
                }
                #pragma unroll
                for (int fn = 0; fn < 4; fn++) {
                    int n = wn * 32 + fn * 8 + (lane >> 2);
                    uint32_t baddr = bufB + (uint32_t)(n * ROWB + kh * 32 + (lane & 3) * 4);
                    uint32_t b0, b1;
                    asm volatile("ld.shared.b32 %0, [%1];" : "=r"(b0) : "r"(baddr));
                    asm volatile("ld.shared.b32 %0, [%1];" : "=r"(b1) : "r"(baddr + 16));
                    #pragma unroll
                    for (int fm = 0; fm < 4; fm++) {
                        asm volatile(
                            "mma.sync.aligned.m16n8k16.row.col.f32.bf16.bf16.f32 "
                            "{%0,%1,%2,%3},{%4,%5,%6,%7},{%8,%9},{%0,%1,%2,%3};"
                            : "+f"(acc[fm][fn][0]), "+f"(acc[fm][fn][1]),
                              "+f"(acc[fm][fn][2]), "+f"(acc[fm][fn][3])
                            : "r"(a[fm][0]), "r"(a[fm][1]), "r"(a[fm][2]), "r"(a[fm][3]),
                              "r"(b0), "r"(b1));
                    }
                }
            }
        }

        #pragma unroll
        for (int p = 0; p < 4; p++) {
            if (wn == p) {
                #pragma unroll
                for (int fm = 0; fm < 4; fm++) {
                    int r0 = wm * 64 + fm * 16 + (lane >> 2);
                    #pragma unroll
                    for (int ff = 0; ff < 4; ff++) {
                        int cl = ff * 8 + (lane & 3) * 2;
                        dt[r0][cl]         = acc[fm][ff][0];
                        dt[r0][cl + 1]     = acc[fm][ff][1];
                        dt[r0 + 8][cl]     = acc[fm][ff][2];
                        dt[r0 + 8][cl + 1] = acc[fm][ff][3];
                    }
                }
            }
            __syncthreads();
            if (t < 128) {
                int base = nt * 128 + p * 32;
                #pragma unroll 8
                for (int c = 0; c < 32; c++) {
                    float s = __fmaf_rn(-2.0f, dt[t][c], s_csq[base + c]);
                    unsigned u = __float_as_uint(s);
                    u ^= (unsigned)((int)u >> 31) | 0x80000000u;
                    unsigned long long key =
                        ((unsigned long long)u << 32) | (unsigned)(c0 + base + c);
                    insert5(run, key);
                }
            }
            __syncthreads();
        }
    }

    if (t < 128) {
        size_t base = ((size_t)(m0 + t) * NCHUNK + ch) * TOPN;
        #pragma unroll
        for (int i = 0; i < TOPN; i++) g_cand[base + i] = run[i];
    }
}

// ---------------------------------------------------------------------------
// Kernel 4: rescore (round-11 form — best measured at 287us; the round-13
// 64KB bulk-staging variant regressed to 305us via residency loss).
// Stage 40 keys cooperatively; t==0 merges to top-16; one candidate per warp,
// EFT-compensated fp32 rescore (fp64-grade ordering); t==0 exact sort.
// Output: out[0..20479] = distances, out[20480..40959] = indices as float.
// ---------------------------------------------------------------------------
__global__ __launch_bounds__(512) void rescore_kernel(
    const float* __restrict__ ctx, float* __restrict__ out, int out_size)
{
    __shared__ __align__(16) float s_q[D_];
    __shared__ unsigned long long s_keys[NCAND];
    __shared__ int    s_idx[NRESC];
    __shared__ double s_d2[NRESC];

    const int row  = blockIdx.x;
    const int b    = row / NQ_;
    const int t    = threadIdx.x;
    const int warp = t >> 5;
    const int lane = t & 31;

    if (t < NCAND) s_keys[t] = g_cand[(size_t)row * NCAND + t];
    {
        const float4* src = (const float4*)(g_qproj + (size_t)row * D_);
        float4* dst = (float4*)s_q;
        for (int i = t; i < D_ / 4; i += 512) dst[i] = src[i];
    }
    __syncthreads();

    if (t == 0) {
        unsigned long long best[NRESC];
        #pragma unroll
        for (int i = 0; i < NRESC; i++) best[i] = ~0ull;
        #pragma unroll
        for (int i = 0; i < NCAND; i++) {
            unsigned long long key = s_keys[i];
            if (key < best[NRESC - 1]) {
                int j = NRESC - 1;
                while (j > 0 && best[j - 1] > key) { best[j] = best[j - 1]; j--; }
                best[j] = key;
            }
        }
        #pragma unroll
        for (int i = 0; i < NRESC; i++) s_idx[i] = (int)(best[i] & 0xffffffffu);
    }
    __syncthreads();

    {
        int idx = s_idx[warp];
        const float4* c4 = (const float4*)(ctx + ((size_t)b * NC_ + idx) * D_);
        const float4* q4 = (const float4*)s_q;
        float hi = 0.0f, lo = 0.0f;
        #pragma unroll
        for (int it = 0; it < D_ / 128; it++) {
            float4 qv = q4[lane + it * 32];
            float4 cv = c4[lane + it * 32];
            acc_sqdiff(qv.x, cv.x, hi, lo);
            acc_sqdiff(qv.y, cv.y, hi, lo);
            acc_sqdiff(qv.z, cv.z, hi, lo);
            acc_sqdiff(qv.w, cv.w, hi, lo);
        }
        double acc = (double)hi + (double)lo;
        #pragma unroll
        for (int off = 16; off; off >>= 1)
            acc += __shfl_xor_sync(0xffffffffu, acc, off);
        if (lane == 0) s_d2[warp] = acc;
    }
    __syncthreads();

    if (t == 0) {
        double d2l[NRESC]; int idl[NRESC];
        #pragma unroll
        for (int i = 0; i < NRESC; i++) { d2l[i] = s_d2[i]; idl[i] = s_idx[i]; }
        const bool write_idx = (out_size >= 2 * NROWS * TOPN);
        #pragma unroll
        for (int k = 0; k < TOPN; k++) {
            int m = k;
            for (int j = k + 1; j < NRESC; j++)
                if (d2l[j] < d2l[m] || (d2l[j] == d2l[m] && idl[j] < idl[m])) m = j;
            double td = d2l[m]; int ti = idl[m];
            d2l[m] = d2l[k]; idl[m] = idl[k];
            d2l[k] = td; idl[k] = ti;
            out[row * TOPN + k] = (float)sqrt(td);
            if (write_idx)
                out[NROWS * TOPN + row * TOPN + k] = (float)ti;
        }
    }
}

// ---------------------------------------------------------------------------
// Launch: ctxprep forked onto a side stream (capture-legal event fork/join)
// so its ~100us of DRAM traffic overlaps qproj's ~350us of FMA compute.
// Stream/events created once; identical graph every capture (deterministic).
// ---------------------------------------------------------------------------
extern "C" void kernel_launch(void* const* d_in, const int* in_sizes, int n_in,
                              void* d_out, int out_size)
{
    const float* Q    = (const float*)d_in[0];   // [4,1024,1024]
    const float* C    = (const float*)d_in[1];   // [4,16384,1024]
    const float* W    = (const float*)d_in[2];   // [1024,1024]
    const float* bias = (const float*)d_in[3];   // [1024]
    float* out = (float*)d_out;

    static cudaStream_t s2 = nullptr;
    static cudaEvent_t evFork = nullptr, evJoin = nullptr;
    if (s2 == nullptr) {
        cudaStreamCreateWithFlags(&s2, cudaStreamNonBlocking);
        cudaEventCreateWithFlags(&evFork, cudaEventDisableTiming);
        cudaEventCreateWithFlags(&evJoin, cudaEventDisableTiming);
        cudaFuncSetAttribute(screen_kernel,
                             cudaFuncAttributeMaxDynamicSharedMemorySize, SM_SCRN);
    }

    // fork: ctxprep (reads only C) runs concurrently with qproj
    cudaEventRecord(evFork, 0);
    cudaStreamWaitEvent(s2, evFork, 0);
    ctxprep_kernel<<<(B_ * NC_ * 32 + 255) / 256, 256, 0, s2>>>(C);
    cudaEventRecord(evJoin, s2);

    qproj_kernel<<<dim3(D_ / 128, NROWS / 128), 256>>>(Q, W, bias);

    // join: screen needs both g_qp_bf (qproj) and g_ctx_bf/g_csq (ctxprep)
    cudaStreamWaitEvent(0, evJoin, 0);

    screen_kernel<<<dim3(NCHUNK, NQ_ / 128, B_), 256, SM_SCRN>>>();
    rescore_kernel<<<NROWS, 512>>>(C, out, out_size);
}

// round 15
// speedup vs baseline: 1.2724x; 1.2489x over previous
#include <cuda_runtime.h>
#include <cuda_bf16.h>
#include <cstdint>

// Problem constants (fixed by the reference)
#define B_      4
#define NQ_     1024
#define NC_     16384
#define D_      1024
#define TOPN    5
#define NCHUNK  8
#define CHUNK   (NC_ / NCHUNK)   // 2048
#define NROWS   (B_ * NQ_)       // 4096
#define NRESC   8                // candidates rescored per row (gap rank5->8 ~70 d2-units >> bf16 screen noise ~0.5)
#define NCAND   (NCHUNK * TOPN)  // 40 screened keys per row

// Screen tiling (mma.sync path — tcgen05 PTX rejected: harness emits compute_103,
// arch-specific tcgen05 needs compute_103a)
#define KT      64                        // k-tile (bf16 elems)
#define NKT     (D_ / KT)                 // 16
#define ROWB    144                       // bytes/row in smem tile (8 chunks + pad)
#define STG_A   (128 * ROWB)              // 18432 B per A tile
#define STG     (2 * STG_A)               // 36864 B per stage (A+B)
#define SM_DT   (2 * STG)                 // 73728: dt offset
#define SM_CSQ  (SM_DT + 128 * 33 * 4)    // 90624: csq offset
#define SM_SCRN (SM_CSQ + CHUNK * 4)      // 98816 total dynamic smem

// ---------------------------------------------------------------------------
// Scratch (no allocations allowed -> __device__ globals, device-code refs only)
// ---------------------------------------------------------------------------
__device__ float          g_qproj[NROWS * D_];            // fp32 q_proj
__device__ __nv_bfloat16  g_qp_bf[NROWS * D_];            // bf16 q_proj
__device__ __nv_bfloat16  g_ctx_bf[(size_t)B_ * NC_ * D_];// bf16 ctx
__device__ float          g_csq[B_ * NC_];
__device__ unsigned long long g_cand[NROWS * NCAND];

// ---------------------------------------------------------------------------
__device__ __forceinline__ void insert5(unsigned long long* run, unsigned long long key) {
    if (key < run[4]) {
        run[4] = key;
        if (run[4] < run[3]) { unsigned long long t = run[3]; run[3] = run[4]; run[4] = t; }
        if (run[3] < run[2]) { unsigned long long t = run[2]; run[2] = run[3]; run[3] = t; }
        if (run[2] < run[1]) { unsigned long long t = run[1]; run[1] = run[2]; run[2] = t; }
        if (run[1] < run[0]) { unsigned long long t = run[0]; run[0] = run[1]; run[1] = t; }
    }
}

__device__ __forceinline__ uint32_t smem_u32(const void* p) {
    uint32_t r;
    asm("{ .reg .u64 t; cvta.to.shared.u64 t, %1; cvt.u32.u64 %0, t; }" : "=r"(r) : "l"(p));
    return r;
}

__device__ __forceinline__ void cpa16(uint32_t dst, const void* src) {
    asm volatile("cp.async.cg.shared.global [%0], [%1], 16;" :: "r"(dst), "l"(src));
}

// Error-free-transformation helpers (valid under round-to-nearest):
__device__ __forceinline__ void two_sum(float a, float b, float& s, float& e) {
    s = __fadd_rn(a, b);
    float bb = __fsub_rn(s, a);
    float t1 = __fsub_rn(s, bb);
    float t2 = __fsub_rn(a, t1);
    float t3 = __fsub_rn(b, bb);
    e = __fadd_rn(t2, t3);
}

// EFT accumulation of one squared difference (q - c)^2 into (hi, lo):
// exact except e*e (<= 2^-48 relative) and lo's own fp32 rounding (~1e-9 abs).
__device__ __forceinline__ void acc_sqdiff(float q, float c, float& hi, float& lo) {
    float s, e;
    two_sum(q, __fmul_rn(-1.0f, c), s, e);
    float p  = __fmul_rn(s, s);
    float pe = __fmaf_rn(s, s, -p);
    float small = __fmaf_rn(__fmul_rn(2.0f, s), e, pe);
    float s1, e1;
    two_sum(hi, p, s1, e1);
    hi = s1;
    lo = __fadd_rn(lo, __fadd_rn(e1, small));
}

// ---------------------------------------------------------------------------
// Kernel 1: q_proj = Q @ W^T + b (fp32 SIMT SGEMM) + bf16 copy for the screen.
// Correctness-load-bearing rounding realization: the per-output FFMA chain
// (one fmaf per k, ascending k) is UNCHANGED. This round adds only register
// prefetch of the next k-step's loads (staging change, arithmetic identical)
// to hide the ~577cyc LDG latency behind the 512-FFMA compute block.
// ---------------------------------------------------------------------------
__global__ __launch_bounds__(256, 2) void qproj_kernel(
    const float* __restrict__ Q, const float* __restrict__ W,
    const float* __restrict__ bias)
{
    __shared__ __align__(16) float As[8][132];
    __shared__ __align__(16) float Bs[8][132];

    const int t  = threadIdx.x;
    const int tx = t & 15, ty = t >> 4;
    const int m0 = blockIdx.y * 128, n0 = blockIdx.x * 128;
    const int lr = t >> 1;
    const int lk = (t & 1) * 4;

    const float* Ap = Q + (size_t)(m0 + lr) * D_ + lk;
    const float* Bp = W + (size_t)(n0 + lr) * D_ + lk;

    float acc[8][8];
    #pragma unroll
    for (int i = 0; i < 8; i++)
        #pragma unroll
        for (int j = 0; j < 8; j++) acc[i][j] = 0.0f;

    float4 av = *(const float4*)(Ap);
    float4 bv = *(const float4*)(Bp);

    for (int k0 = 0; k0 < D_; k0 += 8) {
        __syncthreads();
        As[lk + 0][lr] = av.x; As[lk + 1][lr] = av.y;
        As[lk + 2][lr] = av.z; As[lk + 3][lr] = av.w;
        Bs[lk + 0][lr] = bv.x; Bs[lk + 1][lr] = bv.y;
        Bs[lk + 2][lr] = bv.z; Bs[lk + 3][lr] = bv.w;
        __syncthreads();
        if (k0 + 8 < D_) {                       // prefetch next k-step
            av = *(const float4*)(Ap + k0 + 8);
            bv = *(const float4*)(Bp + k0 + 8);
        }
        #pragma unroll
        for (int kk = 0; kk < 8; kk++) {
            float a[8], b[8];
            *(float4*)(a)     = *(const float4*)(&As[kk][ty * 8]);
            *(float4*)(a + 4) = *(const float4*)(&As[kk][ty * 8 + 4]);
            *(float4*)(b)     = *(const float4*)(&Bs[kk][tx * 8]);
            *(float4*)(b + 4) = *(const float4*)(&Bs[kk][tx * 8 + 4]);
            #pragma unroll
            for (int i = 0; i < 8; i++)
                #pragma unroll
                for (int j = 0; j < 8; j++)
                    acc[i][j] = fmaf(a[i], b[j], acc[i][j]);
        }
    }

    float bj[8];
    #pragma unroll
    for (int j = 0; j < 8; j++) bj[j] = bias[n0 + tx * 8 + j];
    #pragma unroll
    for (int i = 0; i < 8; i++) {
        int row = m0 + ty * 8 + i;
        float o[8];
        #pragma unroll
        for (int j = 0; j < 8; j++) o[j] = __fadd_rn(acc[i][j], bj[j]);
        *(float4*)(g_qproj + (size_t)row * D_ + n0 + tx * 8)     = make_float4(o[0], o[1], o[2], o[3]);
        *(float4*)(g_qproj + (size_t)row * D_ + n0 + tx * 8 + 4) = make_float4(o[4], o[5], o[6], o[7]);
        __nv_bfloat162* dstb = (__nv_bfloat162*)(g_qp_bf + (size_t)row * D_ + n0 + tx * 8);
        dstb[0] = __floats2bfloat162_rn(o[0], o[1]);
        dstb[1] = __floats2bfloat162_rn(o[2], o[3]);
        dstb[2] = __floats2bfloat162_rn(o[4], o[5]);
        dstb[3] = __floats2bfloat162_rn(o[6], o[7]);
    }
}

// ---------------------------------------------------------------------------
// Kernel 2 (fused): one pass over ctx -> bf16 copy + squared row norms.
// Independent of qproj -> launched on a forked stream, overlaps with it.
// ---------------------------------------------------------------------------
__global__ __launch_bounds__(256) void ctxprep_kernel(const float* __restrict__ ctx)
{
    int row  = (blockIdx.x * blockDim.x + threadIdx.x) >> 5;
    int lane = threadIdx.x & 31;
    if (row >= B_ * NC_) return;
    const float4* p = (const float4*)(ctx + (size_t)row * D_);
    uint2* ob = (uint2*)(g_ctx_bf + (size_t)row * D_);
    float s = 0.0f;
    #pragma unroll
    for (int it = 0; it < D_ / 4 / 32; it++) {
        float4 v = p[lane + it * 32];
        s += v.x * v.x + v.y * v.y + v.z * v.z + v.w * v.w;
        union { __nv_bfloat162 h[2]; uint2 u; } pk;
        pk.h[0] = __floats2bfloat162_rn(v.x, v.y);
        pk.h[1] = __floats2bfloat162_rn(v.z, v.w);
        ob[lane + it * 32] = pk.u;
    }
    #pragma unroll
    for (int off = 16; off; off >>= 1) s += __shfl_xor_sync(0xffffffffu, s, off);
    if (lane == 0) g_csq[row] = s;
}

// ---------------------------------------------------------------------------
// Kernel 3: bf16 mma.sync tensor-core screen, 2-stage cp.async pipeline.
// (round-11 version — crossbar-bound; tcgen05 unavailable in this build)
// ---------------------------------------------------------------------------
__global__ __launch_bounds__(256) void screen_kernel()
{
    extern __shared__ __align__(16) char dsm[];
    float (*dt)[33] = (float(*)[33])(dsm + SM_DT);
    float* s_csq    = (float*)(dsm + SM_CSQ);
    const uint32_t smb = smem_u32(dsm);

    const int t    = threadIdx.x;
    const int lane = t & 31;
    const int w    = t >> 5;
    const int wm   = w >> 2;
    const int wn   = w & 3;
    const int ch   = blockIdx.x;
    const int qb   = blockIdx.y;
    const int b    = blockIdx.z;
    const int m0   = b * NQ_ + qb * 128;
    const int c0   = ch * CHUNK;

    for (int i = t; i < CHUNK; i += 256) s_csq[i] = g_csq[b * NC_ + c0 + i];

    int ldr[4], ldc[4];
    #pragma unroll
    for (int i = 0; i < 4; i++) {
        int c = t + i * 256;
        ldr[i] = c >> 3;
        ldc[i] = c & 7;
    }

    const int lm_row  = lane & 15;
    const int lm_half = lane >> 4;

    unsigned long long run[5] = { ~0ull, ~0ull, ~0ull, ~0ull, ~0ull };

    const __nv_bfloat16* gA = g_qp_bf + (size_t)m0 * D_;

    for (int nt = 0; nt < CHUNK / 128; nt++) {
        const __nv_bfloat16* gB = g_ctx_bf + ((size_t)b * NC_ + c0 + nt * 128) * D_;

        float acc[4][4][4];
        #pragma unroll
        for (int fm = 0; fm < 4; fm++)
            #pragma unroll
            for (int fn = 0; fn < 4; fn++)
                #pragma unroll
                for (int v = 0; v < 4; v++) acc[fm][fn][v] = 0.0f;

        #pragma unroll
        for (int i = 0; i < 4; i++) {
            cpa16(smb + ldr[i] * ROWB + ldc[i] * 16,
                  gA + (size_t)ldr[i] * D_ + ldc[i] * 8);
            cpa16(smb + STG_A + ldr[i] * ROWB + ldc[i] * 16,
                  gB + (size_t)ldr[i] * D_ + ldc[i] * 8);
        }
        asm volatile("cp.async.commit_group;");

        for (int kt = 0; kt < NKT; kt++) {
            asm volatile("cp.async.wait_group 0;");
            __syncthreads();
            if (kt + 1 < NKT) {
                uint32_t sb = smb + ((kt + 1) & 1) * STG;
                int koff = (kt + 1) * KT;
                #pragma unroll
                for (int i = 0; i < 4; i++) {
                    cpa16(sb + ldr[i] * ROWB + ldc[i] * 16,
                          gA + (size_t)ldr[i] * D_ + koff + ldc[i] * 8);
                    cpa16(sb + STG_A + ldr[i] * ROWB + ldc[i] * 16,
                          gB + (size_t)ldr[i] * D_ + koff + ldc[i] * 8);
                }
                asm volatile("cp.async.commit_group;");
            }
            const uint32_t bufA = smb + (kt & 1) * STG;
            const uint32_t bufB = bufA + STG_A;

            #pragma unroll
            for (int kh = 0; kh < 4; kh++) {
                uint32_t a[4][4];
                #pragma unroll
                for (int fm = 0; fm < 4; fm++) {
                    int row = wm * 64 + fm * 16 + lm_row;
                    uint32_t addr = bufA + (uint32_t)(row * ROWB + (kh * 2 + lm_half) * 16);
                    asm volatile(
                        "ldmatrix.sync.aligned.m8n8.x4.shared.b16 {%0,%1,%2,%3}, [%4];"
                        : "=r"(a[fm][0]), "=r"(a[fm][1]), "=r"(a[fm][2]), "=r"(a[fm][3])
                        : "r"(addr));
                }
                #pragma unroll
                for (int fn = 0; fn < 4; fn++) {
                    int n = wn * 32 + fn * 8 + (lane >> 2);
                    uint32_t baddr = bufB + (uint32_t)(n * ROWB + kh * 32 + (lane & 3) * 4);
                    uint32_t b0, b1;
                    asm volatile("ld.shared.b32 %0, [%1];" : "=r"(b0) : "r"(baddr));
                    asm volatile("ld.shared.b32 %0, [%1];" : "=r"(b1) : "r"(baddr + 16));
                    #pragma unroll
                    for (int fm = 0; fm < 4; fm++) {
                        asm volatile(
                            "mma.sync.aligned.m16n8k16.row.col.f32.bf16.bf16.f32 "
                            "{%0,%1,%2,%3},{%4,%5,%6,%7},{%8,%9},{%0,%1,%2,%3};"
                            : "+f"(acc[fm][fn][0]), "+f"(acc[fm][fn][1]),
                              "+f"(acc[fm][fn][2]), "+f"(acc[fm][fn][3])
                            : "r"(a[fm][0]), "r"(a[fm][1]), "r"(a[fm][2]), "r"(a[fm][3]),
                              "r"(b0), "r"(b1));
                    }
                }
            }
        }

        #pragma unroll
        for (int p = 0; p < 4; p++) {
            if (wn == p) {
                #pragma unroll
                for (int fm = 0; fm < 4; fm++) {
                    int r0 = wm * 64 + fm * 16 + (lane >> 2);
                    #pragma unroll
                    for (int ff = 0; ff < 4; ff++) {
                        int cl = ff * 8 + (lane & 3) * 2;
                        dt[r0][cl]         = acc[fm][ff][0];
                        dt[r0][cl + 1]     = acc[fm][ff][1];
                        dt[r0 + 8][cl]     = acc[fm][ff][2];
                        dt[r0 + 8][cl + 1] = acc[fm][ff][3];
                    }
                }
            }
            __syncthreads();
            if (t < 128) {
                int base = nt * 128 + p * 32;
                #pragma unroll 8
                for (int c = 0; c < 32; c++) {
                    float s = __fmaf_rn(-2.0f, dt[t][c], s_csq[base + c]);
                    unsigned u = __float_as_uint(s);
                    u ^= (unsigned)((int)u >> 31) | 0x80000000u;
                    unsigned long long key =
                        ((unsigned long long)u << 32) | (unsigned)(c0 + base + c);
                    insert5(run, key);
                }
            }
            __syncthreads();
        }
    }

    if (t < 128) {
        size_t base = ((size_t)(m0 + t) * NCHUNK + ch) * TOPN;
        #pragma unroll
        for (int i = 0; i < TOPN; i++) g_cand[base + i] = run[i];
    }
}

// ---------------------------------------------------------------------------
// Kernel 4: rescore. NRESC 16->8 (order-stats: rank5->rank8 d2 gap ~70 units
// vs bf16 screen noise ~0.5 — escape probability ~0 across all 4096 rows).
// Halves scattered candidate traffic, the dominant cost. 256 threads, one
// candidate per warp; EFT-compensated fp32 rescore (fp64-grade ordering).
// Output: out[0..20479] = distances, out[20480..40959] = indices as float.
// ---------------------------------------------------------------------------
__global__ __launch_bounds__(256) void rescore_kernel(
    const float* __restrict__ ctx, float* __restrict__ out, int out_size)
{
    __shared__ __align__(16) float s_q[D_];
    __shared__ unsigned long long s_keys[NCAND];
    __shared__ int    s_idx[NRESC];
    __shared__ double s_d2[NRESC];

    const int row  = blockIdx.x;
    const int b    = row / NQ_;
    const int t    = threadIdx.x;
    const int warp = t >> 5;     // 0..7: one candidate each
    const int lane = t & 31;

    if (t < NCAND) s_keys[t] = g_cand[(size_t)row * NCAND + t];
    {
        const float4* src = (const float4*)(g_qproj + (size_t)row * D_);
        float4* dst = (float4*)s_q;
        for (int i = t; i < D_ / 4; i += 256) dst[i] = src[i];
    }
    __syncthreads();

    if (t == 0) {
        unsigned long long best[NRESC];
        #pragma unroll
        for (int i = 0; i < NRESC; i++) best[i] = ~0ull;
        #pragma unroll
        for (int i = 0; i < NCAND; i++) {
            unsigned long long key = s_keys[i];
            if (key < best[NRESC - 1]) {
                int j = NRESC - 1;
                while (j > 0 && best[j - 1] > key) { best[j] = best[j - 1]; j--; }
                best[j] = key;
            }
        }
        #pragma unroll
        for (int i = 0; i < NRESC; i++) s_idx[i] = (int)(best[i] & 0xffffffffu);
    }
    __syncthreads();

    {
        int idx = s_idx[warp];
        const float4* c4 = (const float4*)(ctx + ((size_t)b * NC_ + idx) * D_);
        const float4* q4 = (const float4*)s_q;
        float hi = 0.0f, lo = 0.0f;
        #pragma unroll
        for (int it = 0; it < D_ / 128; it++) {
            float4 qv = q4[lane + it * 32];
            float4 cv = c4[lane + it * 32];
            acc_sqdiff(qv.x, cv.x, hi, lo);
            acc_sqdiff(qv.y, cv.y, hi, lo);
            acc_sqdiff(qv.z, cv.z, hi, lo);
            acc_sqdiff(qv.w, cv.w, hi, lo);
        }
        double acc = (double)hi + (double)lo;
        #pragma unroll
        for (int off = 16; off; off >>= 1)
            acc += __shfl_xor_sync(0xffffffffu, acc, off);
        if (lane == 0) s_d2[warp] = acc;
    }
    __syncthreads();

    if (t == 0) {
        double d2l[NRESC]; int idl[NRESC];
        #pragma unroll
        for (int i = 0; i < NRESC; i++) { d2l[i] = s_d2[i]; idl[i] = s_idx[i]; }
        const bool write_idx = (out_size >= 2 * NROWS * TOPN);
        #pragma unroll
        for (int k = 0; k < TOPN; k++) {
            int m = k;
            for (int j = k + 1; j < NRESC; j++)
                if (d2l[j] < d2l[m] || (d2l[j] == d2l[m] && idl[j] < idl[m])) m = j;
            double td = d2l[m]; int ti = idl[m];
            d2l[m] = d2l[k]; idl[m] = idl[k];
            d2l[k] = td; idl[k] = ti;
            out[row * TOPN + k] = (float)sqrt(td);
            if (write_idx)
                out[NROWS * TOPN + row * TOPN + k] = (float)ti;
        }
    }
}

// ---------------------------------------------------------------------------
// Launch: ctxprep forked onto a side stream (capture-legal event fork/join).
// ---------------------------------------------------------------------------
extern "C" void kernel_launch(void* const* d_in, const int* in_sizes, int n_in,
                              void* d_out, int out_size)
{
    const float* Q    = (const float*)d_in[0];   // [4,1024,1024]
    const float* C    = (const float*)d_in[1];   // [4,16384,1024]
    const float* W    = (const float*)d_in[2];   // [1024,1024]
    const float* bias = (const float*)d_in[3];   // [1024]
    float* out = (float*)d_out;

    static cudaStream_t s2 = nullptr;
    static cudaEvent_t evFork = nullptr, evJoin = nullptr;
    if (s2 == nullptr) {
        cudaStreamCreateWithFlags(&s2, cudaStreamNonBlocking);
        cudaEventCreateWithFlags(&evFork, cudaEventDisableTiming);
        cudaEventCreateWithFlags(&evJoin, cudaEventDisableTiming);
        cudaFuncSetAttribute(screen_kernel,
                             cudaFuncAttributeMaxDynamicSharedMemorySize, SM_SCRN);
    }

    // fork: ctxprep (reads only C) runs concurrently with qproj
    cudaEventRecord(evFork, 0);
    cudaStreamWaitEvent(s2, evFork, 0);
    ctxprep_kernel<<<(B_ * NC_ * 32 + 255) / 256, 256, 0, s2>>>(C);
    cudaEventRecord(evJoin, s2);

    qproj_kernel<<<dim3(D_ / 128, NROWS / 128), 256>>>(Q, W, bias);

    // join: screen needs both g_qp_bf (qproj) and g_ctx_bf/g_csq (ctxprep)
    cudaStreamWaitEvent(0, evJoin, 0);

    screen_kernel<<<dim3(NCHUNK, NQ_ / 128, B_), 256, SM_SCRN>>>();
    rescore_kernel<<<NROWS, 256>>>(C, out, out_size);
}